// round 10
// baseline (speedup 1.0000x reference)
#include <cuda_runtime.h>

#define FULL 0xffffffffu
constexpr int NW = 10;   // wires
constexpr int NL = 4;    // layers

// Layer-1 fused gate bases: G = RY(th) * RZ(phi) (om pushed into phase tables)
__device__ float4 g_rot[NW * 2];
// Layers 2-4 RY coefficients: (cos(th/2), sin(th/2))
__device__ float2 g_rycs[3 * NW];
// Phase tables Gamma_g, stored permuted by the accumulated lane relabeling
// M_{g+1}. Entry idx = (k<<5)|bufferLane, halves packed.
//  g_phA = (cr0, cr1, -ci0, -ci1),  g_phB = (ci0, ci1)
__device__ float4 g_phA[3 * 512];
__device__ float2 g_phB[3 * 512];

// ---------------------------------------------------------------------------
// Prep: gate matrices + composed diagonal phase tables. One block, 1024 thr.
// ---------------------------------------------------------------------------
__global__ void prep_kernel(const float* __restrict__ w) {
    __shared__ float s_ang[1024], s_co[1024], s_si[1024];
    int v = threadIdx.x;

    if (v < NL * NW) {
        int l = v / NW, wi = v % NW;
        float phi = w[v * 3 + 0], th = w[v * 3 + 1];
        float s, c;
        sincosf(0.5f * th, &s, &c);
        if (l == 0) {
            float sp, cp;  // e^{-i phi/2} = cp + i sp
            sincosf(-0.5f * phi, &sp, &cp);
            // G = RY(th) RZ(phi)
            g_rot[wi * 2 + 0] = make_float4(c * cp, c * sp, -s * cp, s * sp);
            g_rot[wi * 2 + 1] = make_float4(s * cp, s * sp, c * cp, -c * sp);
        } else {
            g_rycs[(l - 1) * NW + wi] = make_float2(c, s);
        }
    }

    // Rows of M_{g+1}^{-1} (buffer lane from true lane): l_b = parity(row_b & u)
    const int MinvR[3][5] = {{3, 6, 12, 24, 16},
                             {15, 30, 28, 24, 16},
                             {23, 14, 28, 24, 16}};

    for (int g = 0; g < 3; ++g) {
        __syncthreads();
        // delta1 (RZ(om) of layer g) pushed through FULL ring r=g+1
        float a1 = 0.0f;
#pragma unroll
        for (int wi = 0; wi < NW; ++wi) {
            float om = w[(g * NW + wi) * 3 + 2];
            a1 += (((v >> (9 - wi)) & 1) ? 0.5f : -0.5f) * om;
        }
        int u = v, r = g + 1;
#pragma unroll
        for (int wi = 0; wi < NW; ++wi) {
            int pc = 9 - wi, pt = 9 - ((wi + r) % NW);
            if ((u >> pc) & 1) u ^= (1 << pt);
        }
        s_ang[u] = a1;
        __syncthreads();
        // add delta2 (RZ(phi) of layer g+1)
        float a = s_ang[v];
#pragma unroll
        for (int wi = 0; wi < NW; ++wi) {
            float phi = w[((g + 1) * NW + wi) * 3 + 0];
            a += (((v >> (9 - wi)) & 1) ? 0.5f : -0.5f) * phi;
        }
        float si, co;
        sincosf(a, &si, &co);
        s_co[v] = co;
        s_si[v] = si;
        __syncthreads();
        if (v < 512) {
            int v0 = 2 * v, v1 = 2 * v + 1;
            int k = v & 15, L = v >> 4;   // true lane part L
            int l = 0;                    // buffer lane = Minv(L)
#pragma unroll
            for (int b = 0; b < 5; ++b)
                l |= (__popc(MinvR[g][b] & L) & 1) << b;
            int idx = (k << 5) | l;
            g_phA[g * 512 + idx] = make_float4(s_co[v0], s_co[v1], -s_si[v0], -s_si[v1]);
            g_phB[g * 512 + idx] = make_float2(s_si[v0], s_si[v1]);
        }
    }
}

// ---------------------------------------------------------------------------
// Packed f32x2 helpers
// ---------------------------------------------------------------------------
__device__ __forceinline__ float2 f2fma(float2 a, float2 b, float2 c) {
    float2 d;
    asm("{\n\t"
        ".reg .b64 ra, rb, rc, rd;\n\t"
        "mov.b64 ra, {%2, %3};\n\t"
        "mov.b64 rb, {%4, %5};\n\t"
        "mov.b64 rc, {%6, %7};\n\t"
        "fma.rn.f32x2 rd, ra, rb, rc;\n\t"
        "mov.b64 {%0, %1}, rd;\n\t"
        "}"
        : "=f"(d.x), "=f"(d.y)
        : "f"(a.x), "f"(a.y), "f"(b.x), "f"(b.y), "f"(c.x), "f"(c.y));
    return d;
}
__device__ __forceinline__ float2 f2mul(float2 a, float2 b) {
    float2 d;
    asm("{\n\t"
        ".reg .b64 ra, rb, rd;\n\t"
        "mov.b64 ra, {%2, %3};\n\t"
        "mov.b64 rb, {%4, %5};\n\t"
        "mul.rn.f32x2 rd, ra, rb;\n\t"
        "mov.b64 {%0, %1}, rd;\n\t"
        "}"
        : "=f"(d.x), "=f"(d.y)
        : "f"(a.x), "f"(a.y), "f"(b.x), "f"(b.y));
    return d;
}
__device__ __forceinline__ float2 pk(float v) { return make_float2(v, v); }
__device__ __forceinline__ float2 swp(float2 v) { return make_float2(v.y, v.x); }

__device__ __forceinline__ float2 shx2(float2 v, int mask) {
    float2 r;
    r.x = __shfl_xor_sync(FULL, v.x, mask);
    r.y = __shfl_xor_sync(FULL, v.y, mask);
    return r;
}

// ---------------------------------------------------------------------------
// Fused gate bodies. Buffer layout: amp = (bufLane:5 | k:4 | half:1); true lane
// index = M * bufLane (per-phase accumulated GF(2) relabeling).
// ---------------------------------------------------------------------------

// Fused: lane RY (mask X, side parity B) followed by local RY (reg bit KB).
// Gates commute (distinct wires); loop body mixes SHFL and FMA pipes.
template <int X, int B, int KB>
__device__ __forceinline__ void ryLaneLocal(float2 RE[16], float2 IM[16], int lane,
                                            float cL, float sL, float cK, float sK) {
    float sgL = (__popc(lane & B) & 1) ? sL : -sL;
    const float2 cpL = pk(cL), spL = pk(sgL);
    const float2 cpK = pk(cK), spK = pk(sK), npK = pk(-sK);
#pragma unroll
    for (int k = 0; k < 16; ++k) {
        if (!(k & KB)) {
            const int j = k | KB;
            // A (lane RY) on k and j
            float2 oreK = shx2(RE[k], X), oimK = shx2(IM[k], X);
            float2 oreJ = shx2(RE[j], X), oimJ = shx2(IM[j], X);
            float2 aRk = f2fma(cpL, RE[k], f2mul(spL, oreK));
            float2 aIk = f2fma(cpL, IM[k], f2mul(spL, oimK));
            float2 aRj = f2fma(cpL, RE[j], f2mul(spL, oreJ));
            float2 aIj = f2fma(cpL, IM[j], f2mul(spL, oimJ));
            // B (local RY) on the pair
            RE[k] = f2fma(cpK, aRk, f2mul(npK, aRj));
            IM[k] = f2fma(cpK, aIk, f2mul(npK, aIj));
            RE[j] = f2fma(cpK, aRj, f2mul(spK, aRk));
            IM[j] = f2fma(cpK, aIj, f2mul(spK, aIk));
        }
    }
}

// Fused: lane RY (X, B) followed by half-bit RY.
template <int X, int B>
__device__ __forceinline__ void ryLaneHalf(float2 RE[16], float2 IM[16], int lane,
                                           float cL, float sL, float cH, float sH) {
    float sgL = (__popc(lane & B) & 1) ? sL : -sL;
    const float2 cpL = pk(cL), spL = pk(sgL);
    const float2 cpH = pk(cH), ssH = make_float2(-sH, sH);
#pragma unroll
    for (int k = 0; k < 16; ++k) {
        float2 ore = shx2(RE[k], X), oim = shx2(IM[k], X);
        float2 aR = f2fma(cpL, RE[k], f2mul(spL, ore));
        float2 aI = f2fma(cpL, IM[k], f2mul(spL, oim));
        RE[k] = f2fma(cpH, aR, f2mul(ssH, swp(aR)));
        IM[k] = f2fma(cpH, aI, f2mul(ssH, swp(aI)));
    }
}

// Fused complex: lane gate L[4] (mask X, single-bit, M=I) then local gate K[4] (reg bit KB).
template <int X, int KB>
__device__ __forceinline__ void matLaneLocal(float2 RE[16], float2 IM[16], int lane,
                                             const float2 L[4], const float2 K[4]) {
    int bit = (lane & X) ? 1 : 0;
    float2 co = bit ? L[3] : L[0];
    float2 ct = bit ? L[2] : L[1];
    const float2 cox = pk(co.x), coy = pk(co.y), ncoy = pk(-co.y);
    const float2 ctx = pk(ct.x), cty = pk(ct.y), ncty = pk(-ct.y);
    const float2 k00x = pk(K[0].x), k00y = pk(K[0].y), nk00y = pk(-K[0].y);
    const float2 k01x = pk(K[1].x), k01y = pk(K[1].y), nk01y = pk(-K[1].y);
    const float2 k10x = pk(K[2].x), k10y = pk(K[2].y), nk10y = pk(-K[2].y);
    const float2 k11x = pk(K[3].x), k11y = pk(K[3].y), nk11y = pk(-K[3].y);
#pragma unroll
    for (int k = 0; k < 16; ++k) {
        if (!(k & KB)) {
            const int j = k | KB;
            // A on k
            float2 oreK = shx2(RE[k], X), oimK = shx2(IM[k], X);
            float2 aRk = f2fma(ncty, oimK, f2fma(ctx, oreK, f2fma(ncoy, IM[k], f2mul(cox, RE[k]))));
            float2 aIk = f2fma(cty, oreK, f2fma(ctx, oimK, f2fma(coy, RE[k], f2mul(cox, IM[k]))));
            // A on j
            float2 oreJ = shx2(RE[j], X), oimJ = shx2(IM[j], X);
            float2 aRj = f2fma(ncty, oimJ, f2fma(ctx, oreJ, f2fma(ncoy, IM[j], f2mul(cox, RE[j]))));
            float2 aIj = f2fma(cty, oreJ, f2fma(ctx, oimJ, f2fma(coy, RE[j], f2mul(cox, IM[j]))));
            // B (complex local) on the pair
            RE[k] = f2fma(nk01y, aIj, f2fma(k01x, aRj, f2fma(nk00y, aIk, f2mul(k00x, aRk))));
            IM[k] = f2fma(k01y, aRj, f2fma(k01x, aIj, f2fma(k00y, aRk, f2mul(k00x, aIk))));
            RE[j] = f2fma(nk11y, aIj, f2fma(k11x, aRj, f2fma(nk10y, aIk, f2mul(k10x, aRk))));
            IM[j] = f2fma(k11y, aRj, f2fma(k11x, aIj, f2fma(k10y, aRk, f2mul(k10x, aIk))));
        }
    }
}

// Fused complex: lane gate L[4] (mask X) then half-bit complex gate H[4].
template <int X>
__device__ __forceinline__ void matLaneHalf(float2 RE[16], float2 IM[16], int lane,
                                            const float2 L[4], const float2 H[4]) {
    int bit = (lane & X) ? 1 : 0;
    float2 co = bit ? L[3] : L[0];
    float2 ct = bit ? L[2] : L[1];
    const float2 cox = pk(co.x), coy = pk(co.y), ncoy = pk(-co.y);
    const float2 ctx = pk(ct.x), cty = pk(ct.y), ncty = pk(-ct.y);
    // half-gate row-packed coefficients: rows (H00|H10), (H01|H11)
    const float2 c00x = make_float2(H[0].x, H[2].x), c00y = make_float2(H[0].y, H[2].y);
    const float2 c01x = make_float2(H[1].x, H[3].x), c01y = make_float2(H[1].y, H[3].y);
    const float2 n00y = make_float2(-H[0].y, -H[2].y), n01y = make_float2(-H[1].y, -H[3].y);
#pragma unroll
    for (int k = 0; k < 16; ++k) {
        float2 ore = shx2(RE[k], X), oim = shx2(IM[k], X);
        float2 aR = f2fma(ncty, oim, f2fma(ctx, ore, f2fma(ncoy, IM[k], f2mul(cox, RE[k]))));
        float2 aI = f2fma(cty, ore, f2fma(ctx, oim, f2fma(coy, RE[k], f2mul(cox, IM[k]))));
        float a0r = aR.x, a0i = aI.x, a1r = aR.y, a1i = aI.y;
        RE[k] = f2fma(n01y, pk(a1i), f2fma(c01x, pk(a1r),
                 f2fma(n00y, pk(a0i), f2mul(c00x, pk(a0r)))));
        IM[k] = f2fma(c01y, pk(a1r), f2fma(c01x, pk(a1i),
                 f2fma(c00y, pk(a0r), f2mul(c00x, pk(a0i)))));
    }
}

// Gamma (composed diagonal): coalesced table loads
__device__ __forceinline__ void applyPhase(float2 RE[16], float2 IM[16], int lane, int g) {
    const float4* __restrict__ A = g_phA + g * 512 + lane;
    const float2* __restrict__ Bv = g_phB + g * 512 + lane;
#pragma unroll
    for (int k = 0; k < 16; ++k) {
        float4 a = A[k << 5];
        float2 ci = Bv[k << 5];
        float2 cr = make_float2(a.x, a.y), nci = make_float2(a.z, a.w);
        float2 nre = f2fma(cr, RE[k], f2mul(nci, IM[k]));
        float2 nim = f2fma(cr, IM[k], f2mul(ci, RE[k]));
        RE[k] = nre; IM[k] = nim;
    }
}

// ---------------------------------------------------------------------------
// CNOT primitives
// ---------------------------------------------------------------------------
template <int TM>
__device__ __forceinline__ void predSwapK(float2 RE[16], float2 IM[16], bool c1) {
#pragma unroll
    for (int k = 0; k < 16; ++k) {
        if (!(k & TM)) {
            float2 a = RE[k], b = RE[k | TM];
            RE[k] = c1 ? b : a; RE[k | TM] = c1 ? a : b;
            float2 e = IM[k], f = IM[k | TM];
            IM[k] = c1 ? f : e; IM[k | TM] = c1 ? e : f;
        }
    }
}
template <int CM, int TM>
__device__ __forceinline__ void localCnot(float2 RE[16], float2 IM[16]) {
#pragma unroll
    for (int k = 0; k < 16; ++k) {
        if ((k & CM) && !(k & TM)) {
            float2 a = RE[k]; RE[k] = RE[k | TM]; RE[k | TM] = a;
            float2 b = IM[k]; IM[k] = IM[k | TM]; IM[k | TM] = b;
        }
    }
}
template <int CM>
__device__ __forceinline__ void ctrlK_swpHalf(float2 RE[16], float2 IM[16]) {
#pragma unroll
    for (int k = 0; k < 16; ++k) {
        if (k & CM) { RE[k] = swp(RE[k]); IM[k] = swp(IM[k]); }
    }
}
template <int CM, int X>
__device__ __forceinline__ void ctrlK_laneShfl(float2 RE[16], float2 IM[16]) {
#pragma unroll
    for (int k = 0; k < 16; ++k) {
        if (k & CM) { RE[k] = shx2(RE[k], X); IM[k] = shx2(IM[k], X); }
    }
}
template <int X>
__device__ __forceinline__ void halfCtrl_laneShfl(float2 RE[16], float2 IM[16]) {
#pragma unroll
    for (int k = 0; k < 16; ++k) {
        RE[k].y = __shfl_xor_sync(FULL, RE[k].y, X);
        IM[k].y = __shfl_xor_sync(FULL, IM[k].y, X);
    }
}

// ---------------------------------------------------------------------------
// Rings (lane-lane composed blocks deferred via relabeling M)
// ---------------------------------------------------------------------------
// Ring 1, under M1 (rows [31,30,28,24,16]; Minv cols: c4=24)
__device__ __forceinline__ void ring1(float2 RE[16], float2 IM[16], int lane) {
    predSwapK<8>(RE, IM, __popc(lane & 31) & 1);  // w4: CNOT(4,5)
    localCnot<8, 4>(RE, IM);                      // w5: CNOT(5,6)
    localCnot<4, 2>(RE, IM);                      // w6: CNOT(6,7)
    localCnot<2, 1>(RE, IM);                      // w7: CNOT(7,8)
    ctrlK_swpHalf<1>(RE, IM);                     // w8: CNOT(8,9)
    halfCtrl_laneShfl<24>(RE, IM);                // w9: CNOT(9,0)
}
// Ring 2, under M2 (rows [19,6,12,24,16]; Minv cols: c3=15, c4=30)
__device__ __forceinline__ void ring2(float2 RE[16], float2 IM[16], int lane) {
    predSwapK<8>(RE, IM, __popc(lane & 6) & 1);   // w3: CNOT(3,5)
    predSwapK<4>(RE, IM, __popc(lane & 19) & 1);  // w4: CNOT(4,6)
    localCnot<8, 2>(RE, IM);                      // w5: CNOT(5,7)
    localCnot<4, 1>(RE, IM);                      // w6: CNOT(6,8)
    ctrlK_swpHalf<2>(RE, IM);                     // w7: CNOT(7,9)
    ctrlK_laneShfl<1, 30>(RE, IM);                // w8: CNOT(8,0)
    halfCtrl_laneShfl<15>(RE, IM);                // w9: CNOT(9,1)
}
// Ring 3, under M3 (rows [11,22,12,24,16]; Minv cols: c2=7, c3=14, c4=29)
__device__ __forceinline__ void ring3(float2 RE[16], float2 IM[16], int lane) {
    predSwapK<8>(RE, IM, __popc(lane & 12) & 1);  // w2: CNOT(2,5)
    predSwapK<4>(RE, IM, __popc(lane & 22) & 1);  // w3: CNOT(3,6)
    predSwapK<2>(RE, IM, __popc(lane & 11) & 1);  // w4: CNOT(4,7)
    localCnot<8, 1>(RE, IM);                      // w5: CNOT(5,8)
    ctrlK_swpHalf<4>(RE, IM);                     // w6: CNOT(6,9)
    ctrlK_laneShfl<2, 29>(RE, IM);                // w7: CNOT(7,0)
    ctrlK_laneShfl<1, 14>(RE, IM);                // w8: CNOT(8,1)
    halfCtrl_laneShfl<7>(RE, IM);                 // w9: CNOT(9,2)
}

// ---------------------------------------------------------------------------
// Layer-1 fused coefficient builder: F = [RY(th)RZ(phi)] * RY(x*pi/2)
// ---------------------------------------------------------------------------
__device__ __forceinline__ void makeF(int W, float myc, float mys, float2 F[4]) {
    float cw = __shfl_sync(FULL, myc, W);
    float sw = __shfl_sync(FULL, mys, W);
    float4 g0 = g_rot[W * 2 + 0];
    float4 g1 = g_rot[W * 2 + 1];
    float2 U00 = make_float2(g0.x, g0.y), U01 = make_float2(g0.z, g0.w);
    float2 U10 = make_float2(g1.x, g1.y), U11 = make_float2(g1.z, g1.w);
    F[0] = make_float2(fmaf(U00.x, cw, U01.x * sw), fmaf(U00.y, cw, U01.y * sw));
    F[1] = make_float2(fmaf(U01.x, cw, -U00.x * sw), fmaf(U01.y, cw, -U00.y * sw));
    F[2] = make_float2(fmaf(U10.x, cw, U11.x * sw), fmaf(U10.y, cw, U11.y * sw));
    F[3] = make_float2(fmaf(U11.x, cw, -U10.x * sw), fmaf(U11.y, cw, -U10.y * sw));
}

// ---------------------------------------------------------------------------
// Main kernel
// ---------------------------------------------------------------------------
__global__ void __launch_bounds__(128, 4)
vqc_kernel(const float* __restrict__ X, const float* __restrict__ bias,
           float* __restrict__ out, int B) {
    int warp = (blockIdx.x * blockDim.x + threadIdx.x) >> 5;
    int lane = threadIdx.x & 31;
    if (warp >= B) return;

    float x = (lane < NW) ? X[warp * NW + lane] : 0.0f;
    float mys, myc;
    sincosf(x * 0.78539816339744831f, &mys, &myc);

    float2 RE[16], IM[16];
#pragma unroll
    for (int k = 0; k < 16; ++k) { RE[k] = make_float2(0.f, 0.f); IM[k] = make_float2(0.f, 0.f); }
    RE[0].x = (lane == 0) ? 1.0f : 0.0f;

    // ---- Layer 1 (encoding fused; RZ(om) deferred into Gamma_0), pairwise fused ----
    {
        float2 L[4], K[4];
        makeF(0, myc, mys, L); makeF(5, myc, mys, K); matLaneLocal<16, 8>(RE, IM, lane, L, K);
        makeF(1, myc, mys, L); makeF(6, myc, mys, K); matLaneLocal<8, 4>(RE, IM, lane, L, K);
        makeF(2, myc, mys, L); makeF(7, myc, mys, K); matLaneLocal<4, 2>(RE, IM, lane, L, K);
        makeF(3, myc, mys, L); makeF(8, myc, mys, K); matLaneLocal<2, 1>(RE, IM, lane, L, K);
        makeF(4, myc, mys, L); makeF(9, myc, mys, K); matLaneHalf<1>(RE, IM, lane, L, K);
    }
    ring1(RE, IM, lane);   // lane-lane block deferred (M := M1)

    // ---- Layer 2 (under M1) ----
    applyPhase(RE, IM, lane, 0);
    {
        const float2* cs = g_rycs + 0 * NW;
        ryLaneLocal<24, 16, 8>(RE, IM, lane, cs[0].x, cs[0].y, cs[5].x, cs[5].y);
        ryLaneLocal<12, 24, 4>(RE, IM, lane, cs[1].x, cs[1].y, cs[6].x, cs[6].y);
        ryLaneLocal<6, 28, 2>(RE, IM, lane, cs[2].x, cs[2].y, cs[7].x, cs[7].y);
        ryLaneLocal<3, 30, 1>(RE, IM, lane, cs[3].x, cs[3].y, cs[8].x, cs[8].y);
        ryLaneHalf<1, 31>(RE, IM, lane, cs[4].x, cs[4].y, cs[9].x, cs[9].y);
    }
    ring2(RE, IM, lane);   // (M := M2)

    // ---- Layer 3 (under M2) ----
    applyPhase(RE, IM, lane, 1);
    {
        const float2* cs = g_rycs + 1 * NW;
        ryLaneLocal<30, 16, 8>(RE, IM, lane, cs[0].x, cs[0].y, cs[5].x, cs[5].y);
        ryLaneLocal<15, 24, 4>(RE, IM, lane, cs[1].x, cs[1].y, cs[6].x, cs[6].y);
        ryLaneLocal<7, 12, 2>(RE, IM, lane, cs[2].x, cs[2].y, cs[7].x, cs[7].y);
        ryLaneLocal<3, 6, 1>(RE, IM, lane, cs[3].x, cs[3].y, cs[8].x, cs[8].y);
        ryLaneHalf<1, 19>(RE, IM, lane, cs[4].x, cs[4].y, cs[9].x, cs[9].y);
    }
    ring3(RE, IM, lane);   // (M := M3)

    // ---- Layer 4 (under M3); ring 4 fully deferred into measurement ----
    applyPhase(RE, IM, lane, 2);
    {
        const float2* cs = g_rycs + 2 * NW;
        ryLaneLocal<29, 16, 8>(RE, IM, lane, cs[0].x, cs[0].y, cs[5].x, cs[5].y);
        ryLaneLocal<14, 24, 4>(RE, IM, lane, cs[1].x, cs[1].y, cs[6].x, cs[6].y);
        ryLaneLocal<7, 12, 2>(RE, IM, lane, cs[2].x, cs[2].y, cs[7].x, cs[7].y);
        ryLaneLocal<3, 22, 1>(RE, IM, lane, cs[3].x, cs[3].y, cs[8].x, cs[8].y);
        ryLaneHalf<1, 11>(RE, IM, lane, cs[4].x, cs[4].y, cs[9].x, cs[9].y);
    }

    // Measurement: true parity mask e0^e4^e8 -> half ^ k_bit3 ^ parity(l & 24)
    float2 accA = make_float2(0.f, 0.f);
    float2 accB = make_float2(0.f, 0.f);
#pragma unroll
    for (int k = 0; k < 8; ++k)
        accA = f2fma(RE[k], RE[k], f2fma(IM[k], IM[k], accA));
#pragma unroll
    for (int k = 8; k < 16; ++k)
        accB = f2fma(RE[k], RE[k], f2fma(IM[k], IM[k], accB));
    float z = (accA.x - accA.y) - (accB.x - accB.y);
    if (((lane >> 3) ^ (lane >> 4)) & 1) z = -z;
#pragma unroll
    for (int o = 16; o; o >>= 1) z += __shfl_xor_sync(FULL, z, o);
    if (lane == 0) out[warp] = z + bias[0];
}

// ---------------------------------------------------------------------------
extern "C" void kernel_launch(void* const* d_in, const int* in_sizes, int n_in,
                              void* d_out, int out_size) {
    const float* X = (const float*)d_in[0];
    const float* w = (const float*)d_in[1];
    const float* bias = (const float*)d_in[2];
    float* out = (float*)d_out;

    int B = in_sizes[0] / NW;

    prep_kernel<<<1, 1024>>>(w);

    int blocks = (B + 3) / 4;  // 4 warps per 128-thread block
    vqc_kernel<<<blocks, 128>>>(X, bias, out, B);
}

// round 12
// speedup vs baseline: 1.2036x; 1.2036x over previous
#include <cuda_runtime.h>

#define FULL 0xffffffffu
constexpr int NW = 10;   // wires
constexpr int NL = 4;    // layers

// Layer-1 fused gate bases: G = RY(th) * RZ(phi) (om pushed into phase tables)
__device__ float4 g_rot[NW * 2];
// Layers 2-4 RY coefficients: (cos(th/2), sin(th/2))
__device__ float2 g_rycs[3 * NW];
// Phase tables Gamma_g (g=0..2), pair p=(amp>>1) stored TRANSPOSED at
// idx = ((p&15)<<5) | (p>>4)  i.e. [k][lane] order for coalesced warp loads.
//  g_phA = (cr0, cr1, -ci0, -ci1),  g_phB = (ci0, ci1)
__device__ float4 g_phA[3 * 512];
__device__ float2 g_phB[3 * 512];

// ---------------------------------------------------------------------------
// Prep: gate matrices + composed diagonal phase tables. One block, 1024 thr.
// ---------------------------------------------------------------------------
__global__ void prep_kernel(const float* __restrict__ w) {
    __shared__ float s_ang[1024], s_co[1024], s_si[1024];
    int v = threadIdx.x;

    if (v < NL * NW) {
        int l = v / NW, wi = v % NW;
        float phi = w[v * 3 + 0], th = w[v * 3 + 1];
        float s, c;
        sincosf(0.5f * th, &s, &c);
        if (l == 0) {
            float sp, cp;  // e^{-i phi/2} = cp + i sp
            sincosf(-0.5f * phi, &sp, &cp);
            // G = RY(th) RZ(phi)
            g_rot[wi * 2 + 0] = make_float4(c * cp, c * sp, -s * cp, s * sp);
            g_rot[wi * 2 + 1] = make_float4(s * cp, s * sp, c * cp, -c * sp);
        } else {
            g_rycs[(l - 1) * NW + wi] = make_float2(c, s);
        }
    }

    for (int g = 0; g < 3; ++g) {
        __syncthreads();
        // delta1 (RZ(om) of layer g) pushed through ring r=g+1:
        // tmp[pi(u)] = a1(u)
        float a1 = 0.0f;
#pragma unroll
        for (int wi = 0; wi < NW; ++wi) {
            float om = w[(g * NW + wi) * 3 + 2];
            a1 += (((v >> (9 - wi)) & 1) ? 0.5f : -0.5f) * om;
        }
        int u = v, r = g + 1;
#pragma unroll
        for (int wi = 0; wi < NW; ++wi) {
            int pc = 9 - wi, pt = 9 - ((wi + r) % NW);
            if ((u >> pc) & 1) u ^= (1 << pt);
        }
        s_ang[u] = a1;
        __syncthreads();
        // add delta2 (RZ(phi) of layer g+1)
        float a = s_ang[v];
#pragma unroll
        for (int wi = 0; wi < NW; ++wi) {
            float phi = w[((g + 1) * NW + wi) * 3 + 0];
            a += (((v >> (9 - wi)) & 1) ? 0.5f : -0.5f) * phi;
        }
        float si, co;
        sincosf(a, &si, &co);
        s_co[v] = co;
        s_si[v] = si;
        __syncthreads();
        if (v < 512) {
            int v0 = 2 * v, v1 = 2 * v + 1;
            // transposed index: [k][lane] with k = v&15, lane = v>>4
            int idx = ((v & 15) << 5) | (v >> 4);
            g_phA[g * 512 + idx] = make_float4(s_co[v0], s_co[v1], -s_si[v0], -s_si[v1]);
            g_phB[g * 512 + idx] = make_float2(s_si[v0], s_si[v1]);
        }
    }
}

// ---------------------------------------------------------------------------
// Packed f32x2 helpers
// ---------------------------------------------------------------------------
__device__ __forceinline__ float2 f2fma(float2 a, float2 b, float2 c) {
    float2 d;
    asm("{\n\t"
        ".reg .b64 ra, rb, rc, rd;\n\t"
        "mov.b64 ra, {%2, %3};\n\t"
        "mov.b64 rb, {%4, %5};\n\t"
        "mov.b64 rc, {%6, %7};\n\t"
        "fma.rn.f32x2 rd, ra, rb, rc;\n\t"
        "mov.b64 {%0, %1}, rd;\n\t"
        "}"
        : "=f"(d.x), "=f"(d.y)
        : "f"(a.x), "f"(a.y), "f"(b.x), "f"(b.y), "f"(c.x), "f"(c.y));
    return d;
}
__device__ __forceinline__ float2 f2mul(float2 a, float2 b) {
    float2 d;
    asm("{\n\t"
        ".reg .b64 ra, rb, rd;\n\t"
        "mov.b64 ra, {%2, %3};\n\t"
        "mov.b64 rb, {%4, %5};\n\t"
        "mul.rn.f32x2 rd, ra, rb;\n\t"
        "mov.b64 {%0, %1}, rd;\n\t"
        "}"
        : "=f"(d.x), "=f"(d.y)
        : "f"(a.x), "f"(a.y), "f"(b.x), "f"(b.y));
    return d;
}
__device__ __forceinline__ float2 pk(float v) { return make_float2(v, v); }
__device__ __forceinline__ float2 swp(float2 v) { return make_float2(v.y, v.x); }

__device__ __forceinline__ float2 shx2(float2 v, int mask) {
    float2 r;
    r.x = __shfl_xor_sync(FULL, v.x, mask);
    r.y = __shfl_xor_sync(FULL, v.y, mask);
    return r;
}
__device__ __forceinline__ float2 shidx2(float2 v, int src) {
    float2 r;
    r.x = __shfl_sync(FULL, v.x, src);
    r.y = __shfl_sync(FULL, v.y, src);
    return r;
}

// ---------------------------------------------------------------------------
// Layout: amplitude index bit for wire W is p = 9 - W.
//   bits 9..5 -> lane bits, bits 4..1 -> register index, bit 0 -> packed half
// ---------------------------------------------------------------------------

// General complex 2x2 on wire W (layer 1 only)
template <int W>
__device__ __forceinline__ void applyMat(float2 RE[16], float2 IM[16], int lane,
                                         float2 U00, float2 U01, float2 U10, float2 U11) {
    constexpr int p = 9 - W;
    if constexpr (p >= 5) {
        constexpr int lb = p - 5;
        int bit = (lane >> lb) & 1;
        float2 co = bit ? U11 : U00;
        float2 ct = bit ? U10 : U01;
        const float2 cox = pk(co.x), coy = pk(co.y), ncoy = pk(-co.y);
        const float2 ctx = pk(ct.x), cty = pk(ct.y), ncty = pk(-ct.y);
#pragma unroll
        for (int k = 0; k < 16; ++k) {
            float2 ore = shx2(RE[k], 1 << lb);
            float2 oim = shx2(IM[k], 1 << lb);
            float2 nre = f2fma(ncty, oim, f2fma(ctx, ore, f2fma(ncoy, IM[k], f2mul(cox, RE[k]))));
            float2 nim = f2fma(cty, ore, f2fma(ctx, oim, f2fma(coy, RE[k], f2mul(cox, IM[k]))));
            RE[k] = nre; IM[k] = nim;
        }
    } else if constexpr (p >= 1) {
        constexpr int kb = 1 << (p - 1);
        const float2 u00x = pk(U00.x), u00y = pk(U00.y), nu00y = pk(-U00.y);
        const float2 u01x = pk(U01.x), u01y = pk(U01.y), nu01y = pk(-U01.y);
        const float2 u10x = pk(U10.x), u10y = pk(U10.y), nu10y = pk(-U10.y);
        const float2 u11x = pk(U11.x), u11y = pk(U11.y), nu11y = pk(-U11.y);
#pragma unroll
        for (int k = 0; k < 16; ++k) {
            if (!(k & kb)) {
                const int j = k | kb;
                float2 a0re = RE[k], a0im = IM[k], a1re = RE[j], a1im = IM[j];
                RE[k] = f2fma(nu01y, a1im, f2fma(u01x, a1re, f2fma(nu00y, a0im, f2mul(u00x, a0re))));
                IM[k] = f2fma(u01y, a1re, f2fma(u01x, a1im, f2fma(u00y, a0re, f2mul(u00x, a0im))));
                RE[j] = f2fma(nu11y, a1im, f2fma(u11x, a1re, f2fma(nu10y, a0im, f2mul(u10x, a0re))));
                IM[j] = f2fma(u11y, a1re, f2fma(u11x, a1im, f2fma(u10y, a0re, f2mul(u10x, a0im))));
            }
        }
    } else {
        const float2 c00x = make_float2(U00.x, U10.x), c00y = make_float2(U00.y, U10.y);
        const float2 c01x = make_float2(U01.x, U11.x), c01y = make_float2(U01.y, U11.y);
        const float2 n00y = make_float2(-U00.y, -U10.y), n01y = make_float2(-U01.y, -U11.y);
#pragma unroll
        for (int k = 0; k < 16; ++k) {
            float a0r = RE[k].x, a0i = IM[k].x, a1r = RE[k].y, a1i = IM[k].y;
            float2 nre = f2fma(n01y, pk(a1i), f2fma(c01x, pk(a1r),
                          f2fma(n00y, pk(a0i), f2mul(c00x, pk(a0r)))));
            float2 nim = f2fma(c01y, pk(a1r), f2fma(c01x, pk(a1i),
                          f2fma(c00y, pk(a0r), f2mul(c00x, pk(a0i)))));
            RE[k] = nre; IM[k] = nim;
        }
    }
}

// Real RY on wire W: 4 f2-ops per register
template <int W>
__device__ __forceinline__ void ryGate(float2 RE[16], float2 IM[16], int lane, float c, float s) {
    constexpr int p = 9 - W;
    if constexpr (p >= 5) {
        constexpr int lb = p - 5;
        int bit = (lane >> lb) & 1;
        float sg = bit ? s : -s;
        const float2 cp = pk(c), sp = pk(sg);
#pragma unroll
        for (int k = 0; k < 16; ++k) {
            float2 ore = shx2(RE[k], 1 << lb);
            float2 oim = shx2(IM[k], 1 << lb);
            RE[k] = f2fma(cp, RE[k], f2mul(sp, ore));
            IM[k] = f2fma(cp, IM[k], f2mul(sp, oim));
        }
    } else if constexpr (p >= 1) {
        constexpr int kb = 1 << (p - 1);
        const float2 cp = pk(c), sp = pk(s), np = pk(-s);
#pragma unroll
        for (int k = 0; k < 16; ++k) {
            if (!(k & kb)) {
                const int j = k | kb;
                float2 a0re = RE[k], a0im = IM[k], a1re = RE[j], a1im = IM[j];
                RE[k] = f2fma(cp, a0re, f2mul(np, a1re));
                IM[k] = f2fma(cp, a0im, f2mul(np, a1im));
                RE[j] = f2fma(cp, a1re, f2mul(sp, a0re));
                IM[j] = f2fma(cp, a1im, f2mul(sp, a0im));
            }
        }
    } else {
        // p == 0: half-swap butterfly
        const float2 cp = pk(c), ss = make_float2(-s, s);
#pragma unroll
        for (int k = 0; k < 16; ++k) {
            RE[k] = f2fma(cp, RE[k], f2mul(ss, swp(RE[k])));
            IM[k] = f2fma(cp, IM[k], f2mul(ss, swp(IM[k])));
        }
    }
}

// Gamma (composed diagonal): per-register phase multiply, coalesced loads
__device__ __forceinline__ void applyPhase(float2 RE[16], float2 IM[16], int lane, int g) {
    const float4* __restrict__ A = g_phA + g * 512 + lane;
    const float2* __restrict__ Bv = g_phB + g * 512 + lane;
#pragma unroll
    for (int k = 0; k < 16; ++k) {
        float4 a = A[k << 5];
        float2 ci = Bv[k << 5];
        float2 cr = make_float2(a.x, a.y), nci = make_float2(a.z, a.w);
        float2 nre = f2fma(cr, RE[k], f2mul(nci, IM[k]));
        float2 nim = f2fma(cr, IM[k], f2mul(ci, RE[k]));
        RE[k] = nre; IM[k] = nim;
    }
}

// ---------------------------------------------------------------------------
// CNOT cases
// ---------------------------------------------------------------------------
template <int CW, int TW>
__device__ __forceinline__ void cnotGate(float2 RE[16], float2 IM[16], int lane) {
    constexpr int pc = 9 - CW, pt = 9 - TW;
    if constexpr (pc >= 1 && pc <= 4 && pt >= 1 && pt <= 4) {
        constexpr int cm = 1 << (pc - 1), tm = 1 << (pt - 1);
#pragma unroll
        for (int k = 0; k < 16; ++k) {
            if ((k & cm) && !(k & tm)) {
                float2 a = RE[k]; RE[k] = RE[k | tm]; RE[k | tm] = a;
                float2 b = IM[k]; IM[k] = IM[k | tm]; IM[k | tm] = b;
            }
        }
    } else if constexpr (pc >= 1 && pc <= 4 && pt >= 5) {
        constexpr int cm = 1 << (pc - 1), tlm = 1 << (pt - 5);
#pragma unroll
        for (int k = 0; k < 16; ++k) {
            if (k & cm) { RE[k] = shx2(RE[k], tlm); IM[k] = shx2(IM[k], tlm); }
        }
    } else if constexpr (pc >= 1 && pc <= 4 && pt == 0) {
        constexpr int cm = 1 << (pc - 1);
#pragma unroll
        for (int k = 0; k < 16; ++k) {
            if (k & cm) { RE[k] = swp(RE[k]); IM[k] = swp(IM[k]); }
        }
    } else if constexpr (pc >= 5 && pt >= 1 && pt <= 4) {
        constexpr int tm = 1 << (pt - 1);
        bool c1 = (lane >> (pc - 5)) & 1;
#pragma unroll
        for (int k = 0; k < 16; ++k) {
            if (!(k & tm)) {
                float2 a = RE[k], b = RE[k | tm];
                RE[k] = c1 ? b : a; RE[k | tm] = c1 ? a : b;
                float2 e = IM[k], f = IM[k | tm];
                IM[k] = c1 ? f : e; IM[k | tm] = c1 ? e : f;
            }
        }
    } else if constexpr (pc >= 5 && pt == 0) {
        bool c1 = (lane >> (pc - 5)) & 1;
#pragma unroll
        for (int k = 0; k < 16; ++k) {
            float2 a = RE[k], b = IM[k];
            RE[k] = c1 ? swp(a) : a;
            IM[k] = c1 ? swp(b) : b;
        }
    } else if constexpr (pc == 0 && pt >= 5) {
        constexpr int tlm = 1 << (pt - 5);
#pragma unroll
        for (int k = 0; k < 16; ++k) {
            RE[k].y = __shfl_xor_sync(FULL, RE[k].y, tlm);
            IM[k].y = __shfl_xor_sync(FULL, IM[k].y, tlm);
        }
    } else if constexpr (pc == 0 && pt >= 1 && pt <= 4) {
        constexpr int tm = 1 << (pt - 1);
#pragma unroll
        for (int k = 0; k < 16; ++k) {
            if (!(k & tm)) {
                float t = RE[k].y; RE[k].y = RE[k | tm].y; RE[k | tm].y = t;
                float u = IM[k].y; IM[k].y = IM[k | tm].y; IM[k | tm].y = u;
            }
        }
    } else {
        constexpr int tlm = 1 << (pt - 5);
        int src = ((lane >> (pc - 5)) & 1) ? (lane ^ tlm) : lane;
#pragma unroll
        for (int k = 0; k < 16; ++k) { RE[k] = shidx2(RE[k], src); IM[k] = shidx2(IM[k], src); }
    }
}

// ---------------------------------------------------------------------------
// Sequencers
// ---------------------------------------------------------------------------
template <int W>
__device__ __forceinline__ void fusedSeq(float2 RE[16], float2 IM[16], int lane,
                                         float myc, float mys) {
    float cw = __shfl_sync(FULL, myc, W);
    float sw = __shfl_sync(FULL, mys, W);
    float4 g0 = g_rot[W * 2 + 0];
    float4 g1 = g_rot[W * 2 + 1];
    float2 U00 = make_float2(g0.x, g0.y), U01 = make_float2(g0.z, g0.w);
    float2 U10 = make_float2(g1.x, g1.y), U11 = make_float2(g1.z, g1.w);
    float2 F00 = make_float2(fmaf(U00.x, cw, U01.x * sw), fmaf(U00.y, cw, U01.y * sw));
    float2 F01 = make_float2(fmaf(U01.x, cw, -U00.x * sw), fmaf(U01.y, cw, -U00.y * sw));
    float2 F10 = make_float2(fmaf(U10.x, cw, U11.x * sw), fmaf(U10.y, cw, U11.y * sw));
    float2 F11 = make_float2(fmaf(U11.x, cw, -U10.x * sw), fmaf(U11.y, cw, -U10.y * sw));
    applyMat<W>(RE, IM, lane, F00, F01, F10, F11);
    if constexpr (W < NW - 1) fusedSeq<W + 1>(RE, IM, lane, myc, mys);
}

template <int W>
__device__ __forceinline__ void rySeq(float2 RE[16], float2 IM[16], int lane,
                                      const float2* __restrict__ cs) {
    float2 p = cs[W];
    ryGate<W>(RE, IM, lane, p.x, p.y);
    if constexpr (W < NW - 1) rySeq<W + 1>(RE, IM, lane, cs);
}

template <int R, int W>
__device__ __forceinline__ void cnotRest(float2 RE[16], float2 IM[16], int lane) {
    cnotGate<W, (W + R) % NW>(RE, IM, lane);
    if constexpr (W < NW - 1) cnotRest<R, W + 1>(RE, IM, lane);
}

template <int R>
__device__ __forceinline__ void cnotLayer(float2 RE[16], float2 IM[16], int lane) {
    int src = lane;
#pragma unroll
    for (int w = 4 - R; w >= 0; --w) {
        int cb = 4 - w, tb = 4 - w - R;
        src ^= (((src >> cb) & 1) << tb);
    }
#pragma unroll
    for (int k = 0; k < 16; ++k) { RE[k] = shidx2(RE[k], src); IM[k] = shidx2(IM[k], src); }
    cnotRest<R, 5 - R>(RE, IM, lane);
}

// ---------------------------------------------------------------------------
// Main kernel
// ---------------------------------------------------------------------------
__global__ void __launch_bounds__(128, 4)
vqc_kernel(const float* __restrict__ X, const float* __restrict__ bias,
           float* __restrict__ out, int B) {
    int warp = (blockIdx.x * blockDim.x + threadIdx.x) >> 5;
    int lane = threadIdx.x & 31;
    if (warp >= B) return;

    float x = (lane < NW) ? X[warp * NW + lane] : 0.0f;
    float mys, myc;
    sincosf(x * 0.78539816339744831f, &mys, &myc);

    float2 RE[16], IM[16];
#pragma unroll
    for (int k = 0; k < 16; ++k) { RE[k] = make_float2(0.f, 0.f); IM[k] = make_float2(0.f, 0.f); }
    RE[0].x = (lane == 0) ? 1.0f : 0.0f;

    // Layer 1 (encoding fused, RZ(om) deferred) + ring 1
    fusedSeq<0>(RE, IM, lane, myc, mys);
    cnotLayer<1>(RE, IM, lane);

    // Layer 2: Gamma_0 + full RY layer + ring 2
    applyPhase(RE, IM, lane, 0);
    rySeq<0>(RE, IM, lane, g_rycs + 0 * NW);
    cnotLayer<2>(RE, IM, lane);

    // Layer 3: Gamma_1 + full RY layer + ring 3
    applyPhase(RE, IM, lane, 1);
    rySeq<0>(RE, IM, lane, g_rycs + 1 * NW);
    cnotLayer<3>(RE, IM, lane);

    // Layer 4: Gamma_2 (MUST stay: it does not commute with RY'PRY'),
    // then only the RYs whose wires {1,5,9} carry the measured parity
    // P = Z1 Z5 Z9 (ring 4 deferred). RYs on other wires commute with P
    // and are dropped.
    applyPhase(RE, IM, lane, 2);
    {
        const float2* cs = g_rycs + 2 * NW;
        float2 p1 = cs[1], p5 = cs[5], p9 = cs[9];
        ryGate<1>(RE, IM, lane, p1.x, p1.y);   // lane gate (amp bit 8)
        ryGate<5>(RE, IM, lane, p5.x, p5.y);   // local gate (amp bit 4)
        ryGate<9>(RE, IM, lane, p9.x, p9.y);   // half gate (amp bit 0)
    }

    // Z on wire 9 through deferred ring 4: parity mask half ^ k_bit3 ^ lane_bit3
    float2 accA = make_float2(0.f, 0.f);
    float2 accB = make_float2(0.f, 0.f);
#pragma unroll
    for (int k = 0; k < 8; ++k)
        accA = f2fma(RE[k], RE[k], f2fma(IM[k], IM[k], accA));
#pragma unroll
    for (int k = 8; k < 16; ++k)
        accB = f2fma(RE[k], RE[k], f2fma(IM[k], IM[k], accB));
    float z = (accA.x - accA.y) - (accB.x - accB.y);
    if ((lane >> 3) & 1) z = -z;
#pragma unroll
    for (int o = 16; o; o >>= 1) z += __shfl_xor_sync(FULL, z, o);
    if (lane == 0) out[warp] = z + bias[0];
}

// ---------------------------------------------------------------------------
extern "C" void kernel_launch(void* const* d_in, const int* in_sizes, int n_in,
                              void* d_out, int out_size) {
    const float* X = (const float*)d_in[0];
    const float* w = (const float*)d_in[1];
    const float* bias = (const float*)d_in[2];
    float* out = (float*)d_out;

    int B = in_sizes[0] / NW;

    prep_kernel<<<1, 1024>>>(w);

    int blocks = (B + 3) / 4;  // 4 warps per 128-thread block
    vqc_kernel<<<blocks, 128>>>(X, bias, out, B);
}

// round 13
// speedup vs baseline: 1.3207x; 1.0974x over previous
#include <cuda_runtime.h>

#define FULL 0xffffffffu
constexpr int NW = 10;   // wires
constexpr int NL = 4;    // layers

// Layer-1 fused gate bases: G = RY(th) * RZ(phi) (om pushed into phase tables)
__device__ float4 g_rot[NW * 2];
// Layers 2-4 RY coefficients: (cos(th/2), sin(th/2))
__device__ float2 g_rycs[3 * NW];
// Phase tables Gamma_g (g=0..2), pair p=(amp>>1) stored TRANSPOSED at
// idx = ((p&15)<<5) | (p>>4)  i.e. [k][lane] order for coalesced warp loads.
//  g_phA = (cr0, cr1, -ci0, -ci1),  g_phB = (ci0, ci1)
__device__ float4 g_phA[3 * 512];
__device__ float2 g_phB[3 * 512];

// ---------------------------------------------------------------------------
// Prep: gate matrices + composed diagonal phase tables. One block, 1024 thr.
// ---------------------------------------------------------------------------
__global__ void prep_kernel(const float* __restrict__ w) {
    __shared__ float s_ang[1024], s_co[1024], s_si[1024];
    int v = threadIdx.x;

    if (v < NL * NW) {
        int l = v / NW, wi = v % NW;
        float phi = w[v * 3 + 0], th = w[v * 3 + 1];
        float s, c;
        sincosf(0.5f * th, &s, &c);
        if (l == 0) {
            float sp, cp;  // e^{-i phi/2} = cp + i sp
            sincosf(-0.5f * phi, &sp, &cp);
            // G = RY(th) RZ(phi)
            g_rot[wi * 2 + 0] = make_float4(c * cp, c * sp, -s * cp, s * sp);
            g_rot[wi * 2 + 1] = make_float4(s * cp, s * sp, c * cp, -c * sp);
        } else {
            g_rycs[(l - 1) * NW + wi] = make_float2(c, s);
        }
    }

    for (int g = 0; g < 3; ++g) {
        __syncthreads();
        // delta1 (RZ(om) of layer g) pushed through ring r=g+1: tmp[pi(u)] = a1(u)
        float a1 = 0.0f;
#pragma unroll
        for (int wi = 0; wi < NW; ++wi) {
            float om = w[(g * NW + wi) * 3 + 2];
            a1 += (((v >> (9 - wi)) & 1) ? 0.5f : -0.5f) * om;
        }
        int u = v, r = g + 1;
#pragma unroll
        for (int wi = 0; wi < NW; ++wi) {
            int pc = 9 - wi, pt = 9 - ((wi + r) % NW);
            if ((u >> pc) & 1) u ^= (1 << pt);
        }
        s_ang[u] = a1;
        __syncthreads();
        // add delta2 (RZ(phi) of layer g+1)
        float a = s_ang[v];
#pragma unroll
        for (int wi = 0; wi < NW; ++wi) {
            float phi = w[((g + 1) * NW + wi) * 3 + 0];
            a += (((v >> (9 - wi)) & 1) ? 0.5f : -0.5f) * phi;
        }
        float si, co;
        sincosf(a, &si, &co);
        s_co[v] = co;
        s_si[v] = si;
        __syncthreads();
        if (v < 512) {
            int v0 = 2 * v, v1 = 2 * v + 1;
            // transposed index: [k][lane] with k = v&15, lane = v>>4
            int idx = ((v & 15) << 5) | (v >> 4);
            g_phA[g * 512 + idx] = make_float4(s_co[v0], s_co[v1], -s_si[v0], -s_si[v1]);
            g_phB[g * 512 + idx] = make_float2(s_si[v0], s_si[v1]);
        }
    }
}

// ---------------------------------------------------------------------------
// Packed f32x2 helpers
// ---------------------------------------------------------------------------
__device__ __forceinline__ float2 f2fma(float2 a, float2 b, float2 c) {
    float2 d;
    asm("{\n\t"
        ".reg .b64 ra, rb, rc, rd;\n\t"
        "mov.b64 ra, {%2, %3};\n\t"
        "mov.b64 rb, {%4, %5};\n\t"
        "mov.b64 rc, {%6, %7};\n\t"
        "fma.rn.f32x2 rd, ra, rb, rc;\n\t"
        "mov.b64 {%0, %1}, rd;\n\t"
        "}"
        : "=f"(d.x), "=f"(d.y)
        : "f"(a.x), "f"(a.y), "f"(b.x), "f"(b.y), "f"(c.x), "f"(c.y));
    return d;
}
__device__ __forceinline__ float2 f2mul(float2 a, float2 b) {
    float2 d;
    asm("{\n\t"
        ".reg .b64 ra, rb, rd;\n\t"
        "mov.b64 ra, {%2, %3};\n\t"
        "mov.b64 rb, {%4, %5};\n\t"
        "mul.rn.f32x2 rd, ra, rb;\n\t"
        "mov.b64 {%0, %1}, rd;\n\t"
        "}"
        : "=f"(d.x), "=f"(d.y)
        : "f"(a.x), "f"(a.y), "f"(b.x), "f"(b.y));
    return d;
}
__device__ __forceinline__ float2 pk(float v) { return make_float2(v, v); }
__device__ __forceinline__ float2 swp(float2 v) { return make_float2(v.y, v.x); }
__device__ __forceinline__ float2 cmul(float2 a, float2 b) {
    return make_float2(a.x * b.x - a.y * b.y, a.x * b.y + a.y * b.x);
}

__device__ __forceinline__ float2 shx2(float2 v, int mask) {
    float2 r;
    r.x = __shfl_xor_sync(FULL, v.x, mask);
    r.y = __shfl_xor_sync(FULL, v.y, mask);
    return r;
}
__device__ __forceinline__ float2 shidx2(float2 v, int src) {
    float2 r;
    r.x = __shfl_sync(FULL, v.x, src);
    r.y = __shfl_sync(FULL, v.y, src);
    return r;
}

// ---------------------------------------------------------------------------
// Layout: amplitude index bit for wire W is p = 9 - W.
//   bits 9..5 -> lane bits, bits 4..1 -> register index, bit 0 -> packed half
// ---------------------------------------------------------------------------

// Column 0 of fused layer-1 gate F = [RY(th)RZ(phi)] * RY(x*pi/2) for wire W.
__device__ __forceinline__ void colF(int W, float myc, float mys,
                                     float2& F00, float2& F10) {
    float cw = __shfl_sync(FULL, myc, W);
    float sw = __shfl_sync(FULL, mys, W);
    float4 g0 = g_rot[W * 2 + 0];
    float4 g1 = g_rot[W * 2 + 1];
    // F[,0] = U * (c, s)^T
    F00 = make_float2(fmaf(g0.x, cw, g0.z * sw), fmaf(g0.y, cw, g0.w * sw));
    F10 = make_float2(fmaf(g1.x, cw, g1.z * sw), fmaf(g1.y, cw, g1.w * sw));
}

// Build the post-layer-1 product state directly:
// amp(v) = prod_w (v_w ? F10_w : F00_w) applied to |0...0>.
__device__ __forceinline__ void buildInit(float2 RE[16], float2 IM[16], int lane,
                                          float myc, float mys) {
    // Lane factor over wires 0..4 (wire W -> lane bit 4-W)
    float2 F00, F10;
    colF(0, myc, mys, F00, F10);
    float2 L = ((lane >> 4) & 1) ? F10 : F00;
#pragma unroll
    for (int W = 1; W < 5; ++W) {
        colF(W, myc, mys, F00, F10);
        float2 pick = ((lane >> (4 - W)) & 1) ? F10 : F00;
        L = cmul(L, pick);
    }
    // Seed with wire 9 (half bit), folding in the lane factor
    colF(9, myc, mys, F00, F10);
    float2 a0 = cmul(L, F00), a1 = cmul(L, F10);
    RE[0] = make_float2(a0.x, a1.x);
    IM[0] = make_float2(a0.y, a1.y);
    // Doubling tree: wire 8 -> reg bit 0, 7 -> 1, 6 -> 2, 5 -> 3
#pragma unroll
    for (int W = 8; W >= 5; --W) {
        colF(W, myc, mys, F00, F10);
        const int kb = 1 << (8 - W);
        const float2 c00 = pk(F00.x), s00 = pk(F00.y), n00 = pk(-F00.y);
        const float2 c10 = pk(F10.x), s10 = pk(F10.y), n10 = pk(-F10.y);
#pragma unroll
        for (int k = 0; k < 16; ++k) {
            if (k < kb) {
                float2 r = RE[k], i = IM[k];
                RE[k | kb] = f2fma(c10, r, f2mul(n10, i));
                IM[k | kb] = f2fma(c10, i, f2mul(s10, r));
                RE[k] = f2fma(c00, r, f2mul(n00, i));
                IM[k] = f2fma(c00, i, f2mul(s00, r));
            }
        }
    }
}

// Real RY on wire W: 4 f2-ops per register
template <int W>
__device__ __forceinline__ void ryGate(float2 RE[16], float2 IM[16], int lane, float c, float s) {
    constexpr int p = 9 - W;
    if constexpr (p >= 5) {
        constexpr int lb = p - 5;
        int bit = (lane >> lb) & 1;
        float sg = bit ? s : -s;
        const float2 cp = pk(c), sp = pk(sg);
#pragma unroll
        for (int k = 0; k < 16; ++k) {
            float2 ore = shx2(RE[k], 1 << lb);
            float2 oim = shx2(IM[k], 1 << lb);
            RE[k] = f2fma(cp, RE[k], f2mul(sp, ore));
            IM[k] = f2fma(cp, IM[k], f2mul(sp, oim));
        }
    } else if constexpr (p >= 1) {
        constexpr int kb = 1 << (p - 1);
        const float2 cp = pk(c), sp = pk(s), np = pk(-s);
#pragma unroll
        for (int k = 0; k < 16; ++k) {
            if (!(k & kb)) {
                const int j = k | kb;
                float2 a0re = RE[k], a0im = IM[k], a1re = RE[j], a1im = IM[j];
                RE[k] = f2fma(cp, a0re, f2mul(np, a1re));
                IM[k] = f2fma(cp, a0im, f2mul(np, a1im));
                RE[j] = f2fma(cp, a1re, f2mul(sp, a0re));
                IM[j] = f2fma(cp, a1im, f2mul(sp, a0im));
            }
        }
    } else {
        // p == 0: half-swap butterfly
        const float2 cp = pk(c), ss = make_float2(-s, s);
#pragma unroll
        for (int k = 0; k < 16; ++k) {
            RE[k] = f2fma(cp, RE[k], f2mul(ss, swp(RE[k])));
            IM[k] = f2fma(cp, IM[k], f2mul(ss, swp(IM[k])));
        }
    }
}

// Gamma (composed diagonal): per-register phase multiply, coalesced loads
__device__ __forceinline__ void applyPhase(float2 RE[16], float2 IM[16], int lane, int g) {
    const float4* __restrict__ A = g_phA + g * 512 + lane;
    const float2* __restrict__ Bv = g_phB + g * 512 + lane;
#pragma unroll
    for (int k = 0; k < 16; ++k) {
        float4 a = A[k << 5];
        float2 ci = Bv[k << 5];
        float2 cr = make_float2(a.x, a.y), nci = make_float2(a.z, a.w);
        float2 nre = f2fma(cr, RE[k], f2mul(nci, IM[k]));
        float2 nim = f2fma(cr, IM[k], f2mul(ci, RE[k]));
        RE[k] = nre; IM[k] = nim;
    }
}

// ---------------------------------------------------------------------------
// CNOT cases
// ---------------------------------------------------------------------------
template <int CW, int TW>
__device__ __forceinline__ void cnotGate(float2 RE[16], float2 IM[16], int lane) {
    constexpr int pc = 9 - CW, pt = 9 - TW;
    if constexpr (pc >= 1 && pc <= 4 && pt >= 1 && pt <= 4) {
        constexpr int cm = 1 << (pc - 1), tm = 1 << (pt - 1);
#pragma unroll
        for (int k = 0; k < 16; ++k) {
            if ((k & cm) && !(k & tm)) {
                float2 a = RE[k]; RE[k] = RE[k | tm]; RE[k | tm] = a;
                float2 b = IM[k]; IM[k] = IM[k | tm]; IM[k | tm] = b;
            }
        }
    } else if constexpr (pc >= 1 && pc <= 4 && pt >= 5) {
        constexpr int cm = 1 << (pc - 1), tlm = 1 << (pt - 5);
#pragma unroll
        for (int k = 0; k < 16; ++k) {
            if (k & cm) { RE[k] = shx2(RE[k], tlm); IM[k] = shx2(IM[k], tlm); }
        }
    } else if constexpr (pc >= 1 && pc <= 4 && pt == 0) {
        constexpr int cm = 1 << (pc - 1);
#pragma unroll
        for (int k = 0; k < 16; ++k) {
            if (k & cm) { RE[k] = swp(RE[k]); IM[k] = swp(IM[k]); }
        }
    } else if constexpr (pc >= 5 && pt >= 1 && pt <= 4) {
        constexpr int tm = 1 << (pt - 1);
        bool c1 = (lane >> (pc - 5)) & 1;
#pragma unroll
        for (int k = 0; k < 16; ++k) {
            if (!(k & tm)) {
                float2 a = RE[k], b = RE[k | tm];
                RE[k] = c1 ? b : a; RE[k | tm] = c1 ? a : b;
                float2 e = IM[k], f = IM[k | tm];
                IM[k] = c1 ? f : e; IM[k | tm] = c1 ? e : f;
            }
        }
    } else if constexpr (pc >= 5 && pt == 0) {
        bool c1 = (lane >> (pc - 5)) & 1;
#pragma unroll
        for (int k = 0; k < 16; ++k) {
            float2 a = RE[k], b = IM[k];
            RE[k] = c1 ? swp(a) : a;
            IM[k] = c1 ? swp(b) : b;
        }
    } else if constexpr (pc == 0 && pt >= 5) {
        constexpr int tlm = 1 << (pt - 5);
#pragma unroll
        for (int k = 0; k < 16; ++k) {
            RE[k].y = __shfl_xor_sync(FULL, RE[k].y, tlm);
            IM[k].y = __shfl_xor_sync(FULL, IM[k].y, tlm);
        }
    } else if constexpr (pc == 0 && pt >= 1 && pt <= 4) {
        constexpr int tm = 1 << (pt - 1);
#pragma unroll
        for (int k = 0; k < 16; ++k) {
            if (!(k & tm)) {
                float t = RE[k].y; RE[k].y = RE[k | tm].y; RE[k | tm].y = t;
                float u = IM[k].y; IM[k].y = IM[k | tm].y; IM[k | tm].y = u;
            }
        }
    } else {
        constexpr int tlm = 1 << (pt - 5);
        int src = ((lane >> (pc - 5)) & 1) ? (lane ^ tlm) : lane;
#pragma unroll
        for (int k = 0; k < 16; ++k) { RE[k] = shidx2(RE[k], src); IM[k] = shidx2(IM[k], src); }
    }
}

// ---------------------------------------------------------------------------
// Sequencers
// ---------------------------------------------------------------------------
template <int W>
__device__ __forceinline__ void rySeq(float2 RE[16], float2 IM[16], int lane,
                                      const float2* __restrict__ cs) {
    float2 p = cs[W];
    ryGate<W>(RE, IM, lane, p.x, p.y);
    if constexpr (W < NW - 1) rySeq<W + 1>(RE, IM, lane, cs);
}

template <int R, int W>
__device__ __forceinline__ void cnotRest(float2 RE[16], float2 IM[16], int lane) {
    cnotGate<W, (W + R) % NW>(RE, IM, lane);
    if constexpr (W < NW - 1) cnotRest<R, W + 1>(RE, IM, lane);
}

template <int R>
__device__ __forceinline__ void cnotLayer(float2 RE[16], float2 IM[16], int lane) {
    int src = lane;
#pragma unroll
    for (int w = 4 - R; w >= 0; --w) {
        int cb = 4 - w, tb = 4 - w - R;
        src ^= (((src >> cb) & 1) << tb);
    }
#pragma unroll
    for (int k = 0; k < 16; ++k) { RE[k] = shidx2(RE[k], src); IM[k] = shidx2(IM[k], src); }
    cnotRest<R, 5 - R>(RE, IM, lane);
}

// ---------------------------------------------------------------------------
// Main kernel
// ---------------------------------------------------------------------------
__global__ void __launch_bounds__(128, 4)
vqc_kernel(const float* __restrict__ X, const float* __restrict__ bias,
           float* __restrict__ out, int B) {
    int warp = (blockIdx.x * blockDim.x + threadIdx.x) >> 5;
    int lane = threadIdx.x & 31;
    if (warp >= B) return;

    float x = (lane < NW) ? X[warp * NW + lane] : 0.0f;
    float mys, myc;
    sincosf(x * 0.78539816339744831f, &mys, &myc);

    float2 RE[16], IM[16];

    // Layer 1 collapses to direct product-state construction:
    // |psi> = tensor_w F_w |0>, amp(v) = prod_w (v_w ? F10_w : F00_w)
    buildInit(RE, IM, lane, myc, mys);
    cnotLayer<1>(RE, IM, lane);

    // Layer 2: Gamma_0 + full RY layer + ring 2
    applyPhase(RE, IM, lane, 0);
    rySeq<0>(RE, IM, lane, g_rycs + 0 * NW);
    cnotLayer<2>(RE, IM, lane);

    // Layer 3: Gamma_1 + full RY layer + ring 3
    applyPhase(RE, IM, lane, 1);
    rySeq<0>(RE, IM, lane, g_rycs + 1 * NW);
    cnotLayer<3>(RE, IM, lane);

    // Layer 4: Gamma_2 + only the RYs on wires {1,5,9} (they carry the
    // measured parity P = Z1 Z5 Z9 after ring-4 deferral; others commute).
    applyPhase(RE, IM, lane, 2);
    {
        const float2* cs = g_rycs + 2 * NW;
        float2 p1 = cs[1], p5 = cs[5], p9 = cs[9];
        ryGate<1>(RE, IM, lane, p1.x, p1.y);   // lane gate (amp bit 8)
        ryGate<5>(RE, IM, lane, p5.x, p5.y);   // local gate (amp bit 4)
        ryGate<9>(RE, IM, lane, p9.x, p9.y);   // half gate (amp bit 0)
    }

    // Z on wire 9 through deferred ring 4: parity mask half ^ k_bit3 ^ lane_bit3
    float2 accA = make_float2(0.f, 0.f);
    float2 accB = make_float2(0.f, 0.f);
#pragma unroll
    for (int k = 0; k < 8; ++k)
        accA = f2fma(RE[k], RE[k], f2fma(IM[k], IM[k], accA));
#pragma unroll
    for (int k = 8; k < 16; ++k)
        accB = f2fma(RE[k], RE[k], f2fma(IM[k], IM[k], accB));
    float z = (accA.x - accA.y) - (accB.x - accB.y);
    if ((lane >> 3) & 1) z = -z;
#pragma unroll
    for (int o = 16; o; o >>= 1) z += __shfl_xor_sync(FULL, z, o);
    if (lane == 0) out[warp] = z + bias[0];
}

// ---------------------------------------------------------------------------
extern "C" void kernel_launch(void* const* d_in, const int* in_sizes, int n_in,
                              void* d_out, int out_size) {
    const float* X = (const float*)d_in[0];
    const float* w = (const float*)d_in[1];
    const float* bias = (const float*)d_in[2];
    float* out = (float*)d_out;

    int B = in_sizes[0] / NW;

    prep_kernel<<<1, 1024>>>(w);

    int blocks = (B + 3) / 4;  // 4 warps per 128-thread block
    vqc_kernel<<<blocks, 128>>>(X, bias, out, B);
}

// round 14
// speedup vs baseline: 1.3608x; 1.0303x over previous
#include <cuda_runtime.h>

#define FULL 0xffffffffu
constexpr int NW = 10;   // wires
constexpr int NL = 4;    // layers

// Layer-1 fused gate bases: G = RY(th) * RZ(phi) (om pushed into phase tables)
__device__ float4 g_rot[NW * 2];
// Layers 2-4 RY coefficients: (cos(th/2), sin(th/2))
__device__ float2 g_rycs[3 * NW];
// Phase tables Gamma_g (g=0..2), pair p=(amp>>1) stored TRANSPOSED at
// idx = ((p&15)<<5) | (p>>4)  i.e. [k][lane] order for coalesced warp loads.
//  g_phA = (cr0, cr1, -ci0, -ci1),  g_phB = (ci0, ci1)
__device__ float4 g_phA[3 * 512];
__device__ float2 g_phB[3 * 512];

// ---------------------------------------------------------------------------
// Prep: gate matrices + composed diagonal phase tables. One block, 1024 thr.
// ---------------------------------------------------------------------------
__global__ void prep_kernel(const float* __restrict__ w) {
    __shared__ float s_ang[1024], s_co[1024], s_si[1024];
    int v = threadIdx.x;

    if (v < NL * NW) {
        int l = v / NW, wi = v % NW;
        float phi = w[v * 3 + 0], th = w[v * 3 + 1];
        float s, c;
        sincosf(0.5f * th, &s, &c);
        if (l == 0) {
            float sp, cp;  // e^{-i phi/2} = cp + i sp
            sincosf(-0.5f * phi, &sp, &cp);
            // G = RY(th) RZ(phi)
            g_rot[wi * 2 + 0] = make_float4(c * cp, c * sp, -s * cp, s * sp);
            g_rot[wi * 2 + 1] = make_float4(s * cp, s * sp, c * cp, -c * sp);
        } else {
            g_rycs[(l - 1) * NW + wi] = make_float2(c, s);
        }
    }

    for (int g = 0; g < 3; ++g) {
        __syncthreads();
        // delta1 (RZ(om) of layer g) pushed through ring r=g+1: tmp[pi(u)] = a1(u)
        float a1 = 0.0f;
#pragma unroll
        for (int wi = 0; wi < NW; ++wi) {
            float om = w[(g * NW + wi) * 3 + 2];
            a1 += (((v >> (9 - wi)) & 1) ? 0.5f : -0.5f) * om;
        }
        int u = v, r = g + 1;
#pragma unroll
        for (int wi = 0; wi < NW; ++wi) {
            int pc = 9 - wi, pt = 9 - ((wi + r) % NW);
            if ((u >> pc) & 1) u ^= (1 << pt);
        }
        s_ang[u] = a1;
        __syncthreads();
        // add delta2 (RZ(phi) of layer g+1)
        float a = s_ang[v];
#pragma unroll
        for (int wi = 0; wi < NW; ++wi) {
            float phi = w[((g + 1) * NW + wi) * 3 + 0];
            a += (((v >> (9 - wi)) & 1) ? 0.5f : -0.5f) * phi;
        }
        float si, co;
        sincosf(a, &si, &co);
        s_co[v] = co;
        s_si[v] = si;
        __syncthreads();
        if (v < 512) {
            int v0 = 2 * v, v1 = 2 * v + 1;
            // transposed index: [k][lane] with k = v&15, lane = v>>4
            int idx = ((v & 15) << 5) | (v >> 4);
            g_phA[g * 512 + idx] = make_float4(s_co[v0], s_co[v1], -s_si[v0], -s_si[v1]);
            g_phB[g * 512 + idx] = make_float2(s_si[v0], s_si[v1]);
        }
    }
}

// ---------------------------------------------------------------------------
// Packed f32x2 helpers
// ---------------------------------------------------------------------------
__device__ __forceinline__ float2 f2fma(float2 a, float2 b, float2 c) {
    float2 d;
    asm("{\n\t"
        ".reg .b64 ra, rb, rc, rd;\n\t"
        "mov.b64 ra, {%2, %3};\n\t"
        "mov.b64 rb, {%4, %5};\n\t"
        "mov.b64 rc, {%6, %7};\n\t"
        "fma.rn.f32x2 rd, ra, rb, rc;\n\t"
        "mov.b64 {%0, %1}, rd;\n\t"
        "}"
        : "=f"(d.x), "=f"(d.y)
        : "f"(a.x), "f"(a.y), "f"(b.x), "f"(b.y), "f"(c.x), "f"(c.y));
    return d;
}
__device__ __forceinline__ float2 f2mul(float2 a, float2 b) {
    float2 d;
    asm("{\n\t"
        ".reg .b64 ra, rb, rd;\n\t"
        "mov.b64 ra, {%2, %3};\n\t"
        "mov.b64 rb, {%4, %5};\n\t"
        "mul.rn.f32x2 rd, ra, rb;\n\t"
        "mov.b64 {%0, %1}, rd;\n\t"
        "}"
        : "=f"(d.x), "=f"(d.y)
        : "f"(a.x), "f"(a.y), "f"(b.x), "f"(b.y));
    return d;
}
__device__ __forceinline__ float2 pk(float v) { return make_float2(v, v); }
__device__ __forceinline__ float2 swp(float2 v) { return make_float2(v.y, v.x); }
__device__ __forceinline__ float2 cmul(float2 a, float2 b) {
    return make_float2(a.x * b.x - a.y * b.y, a.x * b.y + a.y * b.x);
}

__device__ __forceinline__ float2 shx2(float2 v, int mask) {
    float2 r;
    r.x = __shfl_xor_sync(FULL, v.x, mask);
    r.y = __shfl_xor_sync(FULL, v.y, mask);
    return r;
}
__device__ __forceinline__ float2 shidx2(float2 v, int src) {
    float2 r;
    r.x = __shfl_sync(FULL, v.x, src);
    r.y = __shfl_sync(FULL, v.y, src);
    return r;
}

// ---------------------------------------------------------------------------
// Layout: amplitude index bit for wire W is p = 9 - W.
//   bits 9..5 -> lane bits, bits 4..1 -> register index, bit 0 -> packed half
// ---------------------------------------------------------------------------

// Column 0 of fused layer-1 gate F = [RY(th)RZ(phi)] * RY(x*pi/2) for wire W.
__device__ __forceinline__ void colF(int W, float myc, float mys,
                                     float2& F00, float2& F10) {
    float cw = __shfl_sync(FULL, myc, W);
    float sw = __shfl_sync(FULL, mys, W);
    float4 g0 = g_rot[W * 2 + 0];
    float4 g1 = g_rot[W * 2 + 1];
    // F[,0] = U * (c, s)^T
    F00 = make_float2(fmaf(g0.x, cw, g0.z * sw), fmaf(g0.y, cw, g0.w * sw));
    F10 = make_float2(fmaf(g1.x, cw, g1.z * sw), fmaf(g1.y, cw, g1.w * sw));
}

// Build the post-layer-1 product state directly:
// amp(v) = prod_w (v_w ? F10_w : F00_w) applied to |0...0>.
__device__ __forceinline__ void buildInit(float2 RE[16], float2 IM[16], int lane,
                                          float myc, float mys) {
    // Lane factor over wires 0..4 (wire W -> lane bit 4-W)
    float2 F00, F10;
    colF(0, myc, mys, F00, F10);
    float2 L = ((lane >> 4) & 1) ? F10 : F00;
#pragma unroll
    for (int W = 1; W < 5; ++W) {
        colF(W, myc, mys, F00, F10);
        float2 pick = ((lane >> (4 - W)) & 1) ? F10 : F00;
        L = cmul(L, pick);
    }
    // Seed with wire 9 (half bit), folding in the lane factor
    colF(9, myc, mys, F00, F10);
    float2 a0 = cmul(L, F00), a1 = cmul(L, F10);
    RE[0] = make_float2(a0.x, a1.x);
    IM[0] = make_float2(a0.y, a1.y);
    // Doubling tree: wire 8 -> reg bit 0, 7 -> 1, 6 -> 2, 5 -> 3
#pragma unroll
    for (int W = 8; W >= 5; --W) {
        colF(W, myc, mys, F00, F10);
        const int kb = 1 << (8 - W);
        const float2 c00 = pk(F00.x), s00 = pk(F00.y), n00 = pk(-F00.y);
        const float2 c10 = pk(F10.x), s10 = pk(F10.y), n10 = pk(-F10.y);
#pragma unroll
        for (int k = 0; k < 16; ++k) {
            if (k < kb) {
                float2 r = RE[k], i = IM[k];
                RE[k | kb] = f2fma(c10, r, f2mul(n10, i));
                IM[k | kb] = f2fma(c10, i, f2mul(s10, r));
                RE[k] = f2fma(c00, r, f2mul(n00, i));
                IM[k] = f2fma(c00, i, f2mul(s00, r));
            }
        }
    }
}

// Real RY on wire W: 4 f2-ops per register
template <int W>
__device__ __forceinline__ void ryGate(float2 RE[16], float2 IM[16], int lane, float c, float s) {
    constexpr int p = 9 - W;
    if constexpr (p >= 5) {
        constexpr int lb = p - 5;
        int bit = (lane >> lb) & 1;
        float sg = bit ? s : -s;
        const float2 cp = pk(c), sp = pk(sg);
#pragma unroll
        for (int k = 0; k < 16; ++k) {
            float2 ore = shx2(RE[k], 1 << lb);
            float2 oim = shx2(IM[k], 1 << lb);
            RE[k] = f2fma(cp, RE[k], f2mul(sp, ore));
            IM[k] = f2fma(cp, IM[k], f2mul(sp, oim));
        }
    } else if constexpr (p >= 1) {
        constexpr int kb = 1 << (p - 1);
        const float2 cp = pk(c), sp = pk(s), np = pk(-s);
#pragma unroll
        for (int k = 0; k < 16; ++k) {
            if (!(k & kb)) {
                const int j = k | kb;
                float2 a0re = RE[k], a0im = IM[k], a1re = RE[j], a1im = IM[j];
                RE[k] = f2fma(cp, a0re, f2mul(np, a1re));
                IM[k] = f2fma(cp, a0im, f2mul(np, a1im));
                RE[j] = f2fma(cp, a1re, f2mul(sp, a0re));
                IM[j] = f2fma(cp, a1im, f2mul(sp, a0im));
            }
        }
    } else {
        // p == 0: half-swap butterfly
        const float2 cp = pk(c), ss = make_float2(-s, s);
#pragma unroll
        for (int k = 0; k < 16; ++k) {
            RE[k] = f2fma(cp, RE[k], f2mul(ss, swp(RE[k])));
            IM[k] = f2fma(cp, IM[k], f2mul(ss, swp(IM[k])));
        }
    }
}

// Gamma (composed diagonal): per-register phase multiply, coalesced loads
__device__ __forceinline__ void applyPhase(float2 RE[16], float2 IM[16], int lane, int g) {
    const float4* __restrict__ A = g_phA + g * 512 + lane;
    const float2* __restrict__ Bv = g_phB + g * 512 + lane;
#pragma unroll
    for (int k = 0; k < 16; ++k) {
        float4 a = A[k << 5];
        float2 ci = Bv[k << 5];
        float2 cr = make_float2(a.x, a.y), nci = make_float2(a.z, a.w);
        float2 nre = f2fma(cr, RE[k], f2mul(nci, IM[k]));
        float2 nim = f2fma(cr, IM[k], f2mul(ci, RE[k]));
        RE[k] = nre; IM[k] = nim;
    }
}

// ---------------------------------------------------------------------------
// CNOT cases
// ---------------------------------------------------------------------------
template <int CW, int TW>
__device__ __forceinline__ void cnotGate(float2 RE[16], float2 IM[16], int lane) {
    constexpr int pc = 9 - CW, pt = 9 - TW;
    if constexpr (pc >= 1 && pc <= 4 && pt >= 1 && pt <= 4) {
        constexpr int cm = 1 << (pc - 1), tm = 1 << (pt - 1);
#pragma unroll
        for (int k = 0; k < 16; ++k) {
            if ((k & cm) && !(k & tm)) {
                float2 a = RE[k]; RE[k] = RE[k | tm]; RE[k | tm] = a;
                float2 b = IM[k]; IM[k] = IM[k | tm]; IM[k | tm] = b;
            }
        }
    } else if constexpr (pc >= 1 && pc <= 4 && pt >= 5) {
        constexpr int cm = 1 << (pc - 1), tlm = 1 << (pt - 5);
#pragma unroll
        for (int k = 0; k < 16; ++k) {
            if (k & cm) { RE[k] = shx2(RE[k], tlm); IM[k] = shx2(IM[k], tlm); }
        }
    } else if constexpr (pc >= 1 && pc <= 4 && pt == 0) {
        constexpr int cm = 1 << (pc - 1);
#pragma unroll
        for (int k = 0; k < 16; ++k) {
            if (k & cm) { RE[k] = swp(RE[k]); IM[k] = swp(IM[k]); }
        }
    } else if constexpr (pc >= 5 && pt >= 1 && pt <= 4) {
        constexpr int tm = 1 << (pt - 1);
        bool c1 = (lane >> (pc - 5)) & 1;
#pragma unroll
        for (int k = 0; k < 16; ++k) {
            if (!(k & tm)) {
                float2 a = RE[k], b = RE[k | tm];
                RE[k] = c1 ? b : a; RE[k | tm] = c1 ? a : b;
                float2 e = IM[k], f = IM[k | tm];
                IM[k] = c1 ? f : e; IM[k | tm] = c1 ? e : f;
            }
        }
    } else if constexpr (pc >= 5 && pt == 0) {
        bool c1 = (lane >> (pc - 5)) & 1;
#pragma unroll
        for (int k = 0; k < 16; ++k) {
            float2 a = RE[k], b = IM[k];
            RE[k] = c1 ? swp(a) : a;
            IM[k] = c1 ? swp(b) : b;
        }
    } else if constexpr (pc == 0 && pt >= 5) {
        constexpr int tlm = 1 << (pt - 5);
#pragma unroll
        for (int k = 0; k < 16; ++k) {
            RE[k].y = __shfl_xor_sync(FULL, RE[k].y, tlm);
            IM[k].y = __shfl_xor_sync(FULL, IM[k].y, tlm);
        }
    } else if constexpr (pc == 0 && pt >= 1 && pt <= 4) {
        constexpr int tm = 1 << (pt - 1);
#pragma unroll
        for (int k = 0; k < 16; ++k) {
            if (!(k & tm)) {
                float t = RE[k].y; RE[k].y = RE[k | tm].y; RE[k | tm].y = t;
                float u = IM[k].y; IM[k].y = IM[k | tm].y; IM[k | tm].y = u;
            }
        }
    } else {
        constexpr int tlm = 1 << (pt - 5);
        int src = ((lane >> (pc - 5)) & 1) ? (lane ^ tlm) : lane;
#pragma unroll
        for (int k = 0; k < 16; ++k) { RE[k] = shidx2(RE[k], src); IM[k] = shidx2(IM[k], src); }
    }
}

// ---------------------------------------------------------------------------
// Sequencers
// ---------------------------------------------------------------------------
template <int W>
__device__ __forceinline__ void rySeq(float2 RE[16], float2 IM[16], int lane,
                                      const float2* __restrict__ cs) {
    float2 p = cs[W];
    ryGate<W>(RE, IM, lane, p.x, p.y);
    if constexpr (W < NW - 1) rySeq<W + 1>(RE, IM, lane, cs);
}

template <int R, int W>
__device__ __forceinline__ void cnotRest(float2 RE[16], float2 IM[16], int lane) {
    cnotGate<W, (W + R) % NW>(RE, IM, lane);
    if constexpr (W < NW - 1) cnotRest<R, W + 1>(RE, IM, lane);
}

template <int R>
__device__ __forceinline__ void cnotLayer(float2 RE[16], float2 IM[16], int lane) {
    int src = lane;
#pragma unroll
    for (int w = 4 - R; w >= 0; --w) {
        int cb = 4 - w, tb = 4 - w - R;
        src ^= (((src >> cb) & 1) << tb);
    }
#pragma unroll
    for (int k = 0; k < 16; ++k) { RE[k] = shidx2(RE[k], src); IM[k] = shidx2(IM[k], src); }
    cnotRest<R, 5 - R>(RE, IM, lane);
}

// ---------------------------------------------------------------------------
// Main kernel — ONE WARP PER BLOCK: blocks retire independently, so warps on
// an SMSP sit at uncorrelated circuit phases and shuffle/fma phases overlap.
// ---------------------------------------------------------------------------
__global__ void __launch_bounds__(32, 16)
vqc_kernel(const float* __restrict__ X, const float* __restrict__ bias,
           float* __restrict__ out, int B) {
    int warp = blockIdx.x;
    int lane = threadIdx.x;
    if (warp >= B) return;

    float x = (lane < NW) ? X[warp * NW + lane] : 0.0f;
    float mys, myc;
    sincosf(x * 0.78539816339744831f, &mys, &myc);

    float2 RE[16], IM[16];

    // Layer 1 collapses to direct product-state construction:
    // |psi> = tensor_w F_w |0>, amp(v) = prod_w (v_w ? F10_w : F00_w)
    buildInit(RE, IM, lane, myc, mys);
    cnotLayer<1>(RE, IM, lane);

    // Layer 2: Gamma_0 + full RY layer + ring 2
    applyPhase(RE, IM, lane, 0);
    rySeq<0>(RE, IM, lane, g_rycs + 0 * NW);
    cnotLayer<2>(RE, IM, lane);

    // Layer 3: Gamma_1 + full RY layer + ring 3
    applyPhase(RE, IM, lane, 1);
    rySeq<0>(RE, IM, lane, g_rycs + 1 * NW);
    cnotLayer<3>(RE, IM, lane);

    // Layer 4: Gamma_2 + only the RYs on wires {1,5,9} (they carry the
    // measured parity P = Z1 Z5 Z9 after ring-4 deferral; others commute).
    applyPhase(RE, IM, lane, 2);
    {
        const float2* cs = g_rycs + 2 * NW;
        float2 p1 = cs[1], p5 = cs[5], p9 = cs[9];
        ryGate<1>(RE, IM, lane, p1.x, p1.y);   // lane gate (amp bit 8)
        ryGate<5>(RE, IM, lane, p5.x, p5.y);   // local gate (amp bit 4)
        ryGate<9>(RE, IM, lane, p9.x, p9.y);   // half gate (amp bit 0)
    }

    // Z on wire 9 through deferred ring 4: parity mask half ^ k_bit3 ^ lane_bit3
    float2 accA = make_float2(0.f, 0.f);
    float2 accB = make_float2(0.f, 0.f);
#pragma unroll
    for (int k = 0; k < 8; ++k)
        accA = f2fma(RE[k], RE[k], f2fma(IM[k], IM[k], accA));
#pragma unroll
    for (int k = 8; k < 16; ++k)
        accB = f2fma(RE[k], RE[k], f2fma(IM[k], IM[k], accB));
    float z = (accA.x - accA.y) - (accB.x - accB.y);
    if ((lane >> 3) & 1) z = -z;
#pragma unroll
    for (int o = 16; o; o >>= 1) z += __shfl_xor_sync(FULL, z, o);
    if (lane == 0) out[warp] = z + bias[0];
}

// ---------------------------------------------------------------------------
extern "C" void kernel_launch(void* const* d_in, const int* in_sizes, int n_in,
                              void* d_out, int out_size) {
    const float* X = (const float*)d_in[0];
    const float* w = (const float*)d_in[1];
    const float* bias = (const float*)d_in[2];
    float* out = (float*)d_out;

    int B = in_sizes[0] / NW;

    prep_kernel<<<1, 1024>>>(w);

    vqc_kernel<<<B, 32>>>(X, bias, out, B);  // one warp per block
}